// round 2
// baseline (speedup 1.0000x reference)
#include <cuda_runtime.h>
#include <cuda_bf16.h>
#include <math.h>

// Problem dims (fixed by reference setup_inputs)
#define NB    8192   // batch rows
#define FEAT  4096
#define MID   512
#define EMB   256
#define KCODE 512

// ---- scratch (no allocations allowed; __device__ globals) ----
__device__ float g_h[NB * MID];        // encoder hidden           16 MB
__device__ float g_d[NB * MID];        // decoder hidden           16 MB
__device__ float g_sim[NB * KCODE];    // raw dot(encoded, emb_k)  16 MB
__device__ float g_embT[EMB * KCODE];  // emb transposed           0.5 MB
__device__ float g_invn[KCODE];        // 1/(||emb_k|| + 1e-12)

// ============================================================
// SGEMM: C = act(A[MxK] @ B[KxN] + bias), row-major everywhere.
// Tiles: BM=BN=128, BK=16, 256 threads, 8x8 per thread.
// All dims assumed divisible (M%128==0, N%128==0, K%16==0) — true here.
// ============================================================
template<bool RELU, bool HASBIAS>
__global__ __launch_bounds__(256)
void sgemm_kernel(const float* __restrict__ A, const float* __restrict__ Bm,
                  const float* __restrict__ bias, float* __restrict__ C,
                  int M, int N, int K)
{
    __shared__ float As[16][128];   // transposed A tile: As[k][m]
    __shared__ float Bs[16][128];   // Bs[k][n]

    const int tid = threadIdx.x;
    const int bx = blockIdx.x;      // N tile
    const int by = blockIdx.y;      // M tile
    const int tx = tid & 15;        // 0..15  -> 8 cols each
    const int ty = tid >> 4;        // 0..15  -> 8 rows each

    const float* Ag = A + (size_t)by * 128 * K;
    const float* Bg = Bm + (size_t)bx * 128;

    float acc[8][8];
    #pragma unroll
    for (int i = 0; i < 8; i++)
        #pragma unroll
        for (int j = 0; j < 8; j++) acc[i][j] = 0.f;

    for (int k0 = 0; k0 < K; k0 += 16) {
        // load A tile: 128x16 = 512 float4, 2 per thread, store transposed
        #pragma unroll
        for (int i = 0; i < 2; i++) {
            int f4 = tid * 2 + i;
            int r  = f4 >> 2;        // row in tile (0..127)
            int c4 = f4 & 3;         // which float4 along K
            float4 v = *(const float4*)(Ag + (size_t)r * K + k0 + c4 * 4);
            As[c4 * 4 + 0][r] = v.x;
            As[c4 * 4 + 1][r] = v.y;
            As[c4 * 4 + 2][r] = v.z;
            As[c4 * 4 + 3][r] = v.w;
        }
        // load B tile: 16x128 = 512 float4, 2 per thread
        #pragma unroll
        for (int i = 0; i < 2; i++) {
            int f4 = tid * 2 + i;
            int r  = f4 >> 5;        // k row (0..15)
            int c4 = f4 & 31;        // float4 along N
            float4 v = *(const float4*)(Bg + (size_t)(k0 + r) * N + c4 * 4);
            *(float4*)&Bs[r][c4 * 4] = v;
        }
        __syncthreads();

        #pragma unroll
        for (int k = 0; k < 16; k++) {
            float4 a0 = *(const float4*)&As[k][ty * 8];
            float4 a1 = *(const float4*)&As[k][ty * 8 + 4];
            float4 b0 = *(const float4*)&Bs[k][tx * 8];
            float4 b1 = *(const float4*)&Bs[k][tx * 8 + 4];
            float a[8] = {a0.x, a0.y, a0.z, a0.w, a1.x, a1.y, a1.z, a1.w};
            float b[8] = {b0.x, b0.y, b0.z, b0.w, b1.x, b1.y, b1.z, b1.w};
            #pragma unroll
            for (int i = 0; i < 8; i++)
                #pragma unroll
                for (int j = 0; j < 8; j++)
                    acc[i][j] = fmaf(a[i], b[j], acc[i][j]);
        }
        __syncthreads();
    }

    // epilogue
    const int col0 = bx * 128 + tx * 8;
    float bb[8];
    #pragma unroll
    for (int j = 0; j < 8; j++) bb[j] = HASBIAS ? bias[col0 + j] : 0.f;

    #pragma unroll
    for (int i = 0; i < 8; i++) {
        int row = by * 128 + ty * 8 + i;
        float v[8];
        #pragma unroll
        for (int j = 0; j < 8; j++) {
            float t = acc[i][j] + bb[j];
            v[j] = RELU ? fmaxf(t, 0.f) : t;
        }
        float* cp = C + (size_t)row * N + col0;
        *(float4*)(cp)     = make_float4(v[0], v[1], v[2], v[3]);
        *(float4*)(cp + 4) = make_float4(v[4], v[5], v[6], v[7]);
    }
}

// ============================================================
// emb prep: transpose emb [KCODE x EMB] -> embT [EMB x KCODE],
// and inv_norm[k] = 1/(||emb_k|| + 1e-12)
// grid = KCODE blocks, 256 threads (EMB == 256)
// ============================================================
__global__ __launch_bounds__(256)
void prep_emb_kernel(const float* __restrict__ emb,
                     float* __restrict__ embT, float* __restrict__ invn)
{
    int c = blockIdx.x;       // code row
    int t = threadIdx.x;      // dim
    float v = emb[(size_t)c * EMB + t];
    embT[(size_t)t * KCODE + c] = v;

    __shared__ float red[256];
    red[t] = v * v;
    __syncthreads();
    #pragma unroll
    for (int off = 128; off > 0; off >>= 1) {
        if (t < off) red[t] += red[t + off];
        __syncthreads();
    }
    if (t == 0) invn[c] = 1.f / (sqrtf(red[0]) + 1e-12f);
}

// ============================================================
// VQ: per row, argmax_k sim[row,k]*invn[k] (lowest index wins ties,
// matching jnp.argmax). Writes one-hot row and gathers emb[idx].
// grid = NB blocks, 256 threads
// ============================================================
__global__ __launch_bounds__(256)
void vq_kernel(const float* __restrict__ sim, const float* __restrict__ invn,
               const float* __restrict__ emb,
               float* __restrict__ vq_feat, float* __restrict__ onehot)
{
    int row = blockIdx.x;
    int t = threadIdx.x;
    const float* s = sim + (size_t)row * KCODE;

    float v0 = s[t]       * invn[t];
    float v1 = s[t + 256] * invn[t + 256];
    float bv; int bi;
    if (v0 >= v1) { bv = v0; bi = t; } else { bv = v1; bi = t + 256; }

    __shared__ float sv[256];
    __shared__ int   si[256];
    sv[t] = bv; si[t] = bi;
    __syncthreads();
    #pragma unroll
    for (int off = 128; off > 0; off >>= 1) {
        if (t < off) {
            float ov = sv[t + off]; int oi = si[t + off];
            if (ov > sv[t] || (ov == sv[t] && oi < si[t])) { sv[t] = ov; si[t] = oi; }
        }
        __syncthreads();
    }
    int idx = si[0];

    onehot[(size_t)row * KCODE + t]       = (t == idx)       ? 1.f : 0.f;
    onehot[(size_t)row * KCODE + t + 256] = (t + 256 == idx) ? 1.f : 0.f;
    vq_feat[(size_t)row * EMB + t] = emb[(size_t)idx * EMB + t];
}

// ============================================================
// launcher
// ============================================================
extern "C" void kernel_launch(void* const* d_in, const int* in_sizes, int n_in,
                              void* d_out, int out_size)
{
    const float* x      = (const float*)d_in[0];
    const float* enc_w1 = (const float*)d_in[1];
    const float* enc_b1 = (const float*)d_in[2];
    const float* enc_w2 = (const float*)d_in[3];
    const float* enc_b2 = (const float*)d_in[4];
    const float* emb    = (const float*)d_in[5];
    const float* dec_w1 = (const float*)d_in[6];
    const float* dec_b1 = (const float*)d_in[7];
    const float* dec_w2 = (const float*)d_in[8];
    const float* dec_b2 = (const float*)d_in[9];

    float* out = (float*)d_out;
    // output tuple flattened in order:
    float* o_encoded = out;                                   // [NB, EMB]
    float* o_vqfeat  = o_encoded + (size_t)NB * EMB;          // [NB, EMB]
    float* o_onehot  = o_vqfeat  + (size_t)NB * EMB;          // [NB, KCODE]
    float* o_decoded = o_onehot  + (size_t)NB * KCODE;        // [NB, FEAT]
    float* o_emb     = o_decoded + (size_t)NB * FEAT;         // [KCODE, EMB]

    float *h, *dbuf, *sim, *embT, *invn;
    cudaGetSymbolAddress((void**)&h,    g_h);
    cudaGetSymbolAddress((void**)&dbuf, g_d);
    cudaGetSymbolAddress((void**)&sim,  g_sim);
    cudaGetSymbolAddress((void**)&embT, g_embT);
    cudaGetSymbolAddress((void**)&invn, g_invn);

    // 1) emb transpose + inverse norms
    prep_emb_kernel<<<KCODE, 256>>>(emb, embT, invn);

    // 2) h = relu(x @ enc_w1 + enc_b1)   [8192x4096]@[4096x512]
    sgemm_kernel<true, true><<<dim3(MID / 128, NB / 128), 256>>>(
        x, enc_w1, enc_b1, h, NB, MID, FEAT);

    // 3) encoded = h @ enc_w2 + enc_b2   [8192x512]@[512x256]
    sgemm_kernel<false, true><<<dim3(EMB / 128, NB / 128), 256>>>(
        h, enc_w2, enc_b2, o_encoded, NB, EMB, MID);

    // 4) sim = encoded @ emb^T           [8192x256]@[256x512]
    sgemm_kernel<false, false><<<dim3(KCODE / 128, NB / 128), 256>>>(
        o_encoded, embT, nullptr, sim, NB, KCODE, EMB);

    // 5) argmax + onehot + codebook gather
    vq_kernel<<<NB, 256>>>(sim, invn, emb, o_vqfeat, o_onehot);

    // 6) d = relu(vq_feat @ dec_w1 + dec_b1)   [8192x256]@[256x512]
    sgemm_kernel<true, true><<<dim3(MID / 128, NB / 128), 256>>>(
        o_vqfeat, dec_w1, dec_b1, dbuf, NB, MID, EMB);

    // 7) decoded = relu(d @ dec_w2 + dec_b2)   [8192x512]@[512x4096]
    sgemm_kernel<true, true><<<dim3(FEAT / 128, NB / 128), 256>>>(
        dbuf, dec_w2, dec_b2, o_decoded, NB, FEAT, MID);

    // 8) pass-through emb
    cudaMemcpyAsync(o_emb, emb, (size_t)KCODE * EMB * sizeof(float),
                    cudaMemcpyDeviceToDevice, 0);
}

// round 4
// speedup vs baseline: 2.8005x; 2.8005x over previous
#include <cuda_runtime.h>
#include <cuda_bf16.h>
#include <math.h>
#include <stdint.h>

#define NB    8192
#define FEAT  4096
#define MID   512
#define EMB   256
#define KCODE 512

typedef __nv_bfloat16 bf16;

// ------------- scratch (__device__ globals; no allocs allowed) -------------
__device__ bf16 g_x_hi[NB*FEAT],  g_x_lo[NB*FEAT];
__device__ bf16 g_w1t_hi[MID*FEAT], g_w1t_lo[MID*FEAT];   // enc_w1^T [512,4096]
__device__ bf16 g_w2t_hi[EMB*MID],  g_w2t_lo[EMB*MID];    // enc_w2^T [256,512]
__device__ bf16 g_d1t_hi[MID*EMB],  g_d1t_lo[MID*EMB];    // dec_w1^T [512,256]
__device__ bf16 g_d2t_hi[FEAT*MID], g_d2t_lo[FEAT*MID];   // dec_w2^T [4096,512]
__device__ bf16 g_emb_hi[KCODE*EMB], g_emb_lo[KCODE*EMB];
__device__ bf16 g_h_hi[NB*MID],  g_h_lo[NB*MID];
__device__ bf16 g_e_hi[NB*EMB],  g_e_lo[NB*EMB];
__device__ bf16 g_v_hi[NB*EMB],  g_v_lo[NB*EMB];
__device__ bf16 g_dd_hi[NB*MID], g_dd_lo[NB*MID];
__device__ float g_sim[NB*KCODE];
__device__ float g_invn[KCODE];

// ------------- helpers -------------
__device__ __forceinline__ uint32_t smem_u32(const void* p) {
    uint32_t a;
    asm("{ .reg .u64 t; cvta.to.shared.u64 t, %1; cvt.u32.u64 %0, t; }" : "=r"(a) : "l"(p));
    return a;
}
#define SWZ(o) ((o) ^ (((o) >> 3) & 0x70))
#define CP16(dst, src) asm volatile("cp.async.cg.shared.global [%0], [%1], 16;" :: "r"(dst), "l"(src))

__device__ __forceinline__ void ldsm4(uint32_t* r, uint32_t addr) {
    asm volatile("ldmatrix.sync.aligned.m8n8.x4.shared.b16 {%0,%1,%2,%3}, [%4];"
        : "=r"(r[0]), "=r"(r[1]), "=r"(r[2]), "=r"(r[3]) : "r"(addr));
}
__device__ __forceinline__ void mma16816(float* c, const uint32_t* a, const uint32_t* b) {
    asm volatile("mma.sync.aligned.m16n8k16.row.col.f32.bf16.bf16.f32 "
        "{%0,%1,%2,%3}, {%4,%5,%6,%7}, {%8,%9}, {%0,%1,%2,%3};"
        : "+f"(c[0]), "+f"(c[1]), "+f"(c[2]), "+f"(c[3])
        : "r"(a[0]), "r"(a[1]), "r"(a[2]), "r"(a[3]), "r"(b[0]), "r"(b[1]));
}
__device__ __forceinline__ void split2(float v, bf16& h, bf16& l) {
    h = __float2bfloat16(v);
    l = __float2bfloat16(v - __bfloat162float(h));
}

// ============================================================
// split-bf16 GEMM on HMMA (mma.sync):  C[M,N] = act(A @ W + bias)
// A = (Ah,Al) [M,K] row-major bf16 ; B = (Bh,Bl) [N,K] row-major bf16 (W^T).
// C = Ah*Bh + Al*Bh + Ah*Bl, fp32 accum.
// Tile BM=128 x BN=256, BK=64, 256 threads (warps 2x4, warp tile 64x64),
// SW128 smem, cp.async double buffer, ldmatrix fragments.
// ============================================================
#define BM 128
#define BN 256
#define BK 64
#define OFF_AH 0
#define OFF_AL 16384
#define OFF_BH 32768
#define OFF_BL 65536
#define STAGE  98304
#define SMEM_SZ (2 * STAGE)

__device__ __forceinline__ void load_chunk(
    uint32_t st, const bf16* __restrict__ Ah, const bf16* __restrict__ Al,
    const bf16* __restrict__ Bh, const bf16* __restrict__ Bl,
    int m0, int n0, int k0, int K, int tid)
{
    const bf16* pAh = Ah + (size_t)m0 * K + k0;
    const bf16* pAl = Al + (size_t)m0 * K + k0;
    #pragma unroll
    for (int i = 0; i < 4; i++) {             // A: 128 rows x 8 x 16B = 1024 units
        int u = i * 256 + tid;
        int r = u >> 3, c = u & 7;
        uint32_t so = SWZ((uint32_t)(r * 128 + c * 16));
        size_t go = (size_t)r * K + c * 8;
        CP16(st + OFF_AH + so, pAh + go);
        CP16(st + OFF_AL + so, pAl + go);
    }
    const bf16* pBh = Bh + (size_t)n0 * K + k0;
    const bf16* pBl = Bl + (size_t)n0 * K + k0;
    #pragma unroll
    for (int i = 0; i < 8; i++) {             // B: 256 rows x 8 x 16B = 2048 units
        int u = i * 256 + tid;
        int r = u >> 3, c = u & 7;
        uint32_t so = SWZ((uint32_t)(r * 128 + c * 16));
        size_t go = (size_t)r * K + c * 8;
        CP16(st + OFF_BH + so, pBh + go);
        CP16(st + OFF_BL + so, pBl + go);
    }
}

template<bool RELU, bool HASBIAS, bool WF32, bool WSPL>
__global__ __launch_bounds__(256, 1)
void tgemm(const bf16* __restrict__ Ah, const bf16* __restrict__ Al,
           const bf16* __restrict__ Bh, const bf16* __restrict__ Bl,
           const float* __restrict__ bias,
           float* __restrict__ oF, bf16* __restrict__ oH, bf16* __restrict__ oL,
           int M, int N, int K)
{
    extern __shared__ char smem[];
    const uint32_t sb = smem_u32(smem);
    const int tid  = threadIdx.x;
    const int wid  = tid >> 5;
    const int lane = tid & 31;
    const int wm   = wid >> 2;     // 0..1  (M dir, 64 rows each)
    const int wn   = wid & 3;      // 0..3  (N dir, 64 cols each)
    const int m0   = blockIdx.y * BM;
    const int n0   = blockIdx.x * BN;
    const int NC   = K / BK;

    float acc[4][8][4];
    #pragma unroll
    for (int i = 0; i < 4; i++)
        #pragma unroll
        for (int j = 0; j < 8; j++)
            #pragma unroll
            for (int k = 0; k < 4; k++) acc[i][j][k] = 0.f;

    load_chunk(sb, Ah, Al, Bh, Bl, m0, n0, 0, K, tid);
    asm volatile("cp.async.commit_group;" ::: "memory");

    const int g  = lane >> 3;    // ldmatrix quadrant
    const int lr = lane & 7;

    for (int c = 0; c < NC; c++) {
        if (c + 1 < NC) {
            load_chunk(sb + ((c + 1) & 1) * STAGE, Ah, Al, Bh, Bl,
                       m0, n0, (c + 1) * BK, K, tid);
            asm volatile("cp.async.commit_group;" ::: "memory");
            asm volatile("cp.async.wait_group 1;" ::: "memory");
        } else {
            asm volatile("cp.async.wait_group 0;" ::: "memory");
        }
        __syncthreads();

        const uint32_t st = sb + (c & 1) * STAGE;
        #pragma unroll
        for (int ks = 0; ks < 4; ks++) {
            uint32_t afh[16], afl[16], bfr[16];
            // A frags (hi & lo): 4 m16 tiles
            #pragma unroll
            for (int mt = 0; mt < 4; mt++) {
                int row = wm * 64 + mt * 16 + (g & 1) * 8 + lr;
                int k   = ks * 16 + (g >> 1) * 8;
                uint32_t off = SWZ((uint32_t)(row * 128 + k * 2));
                ldsm4(&afh[mt * 4], st + OFF_AH + off);
                ldsm4(&afl[mt * 4], st + OFF_AL + off);
            }
            // B hi frags: 8 n8 tiles (4 x4-loads)
            #pragma unroll
            for (int p = 0; p < 4; p++) {
                int row = wn * 64 + (p * 2 + (g >> 1)) * 8 + lr;
                int k   = ks * 16 + (g & 1) * 8;
                uint32_t off = SWZ((uint32_t)(row * 128 + k * 2));
                ldsm4(&bfr[p * 4], st + OFF_BH + off);
            }
            // pass 1: Ah*Bh ; pass 2: Al*Bh
            #pragma unroll
            for (int mt = 0; mt < 4; mt++)
                #pragma unroll
                for (int nt = 0; nt < 8; nt++) {
                    const uint32_t* b = &bfr[(nt >> 1) * 4 + (nt & 1) * 2];
                    mma16816(acc[mt][nt], &afh[mt * 4], b);
                }
            #pragma unroll
            for (int mt = 0; mt < 4; mt++)
                #pragma unroll
                for (int nt = 0; nt < 8; nt++) {
                    const uint32_t* b = &bfr[(nt >> 1) * 4 + (nt & 1) * 2];
                    mma16816(acc[mt][nt], &afl[mt * 4], b);
                }
            // B lo frags, pass 3: Ah*Bl
            #pragma unroll
            for (int p = 0; p < 4; p++) {
                int row = wn * 64 + (p * 2 + (g >> 1)) * 8 + lr;
                int k   = ks * 16 + (g & 1) * 8;
                uint32_t off = SWZ((uint32_t)(row * 128 + k * 2));
                ldsm4(&bfr[p * 4], st + OFF_BL + off);
            }
            #pragma unroll
            for (int mt = 0; mt < 4; mt++)
                #pragma unroll
                for (int nt = 0; nt < 8; nt++) {
                    const uint32_t* b = &bfr[(nt >> 1) * 4 + (nt & 1) * 2];
                    mma16816(acc[mt][nt], &afh[mt * 4], b);
                }
        }
        __syncthreads();
    }

    // ---- epilogue: regs -> gmem ----
    const int r0 = lane >> 2;          // 0..7
    const int c0 = (lane & 3) * 2;     // 0,2,4,6
    #pragma unroll
    for (int nt = 0; nt < 8; nt++) {
        int col = n0 + wn * 64 + nt * 8 + c0;
        float b0 = 0.f, b1 = 0.f;
        if (HASBIAS) { b0 = __ldg(&bias[col]); b1 = __ldg(&bias[col + 1]); }
        #pragma unroll
        for (int mt = 0; mt < 4; mt++) {
            int rowa = m0 + wm * 64 + mt * 16 + r0;
            float v0 = acc[mt][nt][0] + b0;
            float v1 = acc[mt][nt][1] + b1;
            float v2 = acc[mt][nt][2] + b0;
            float v3 = acc[mt][nt][3] + b1;
            if (RELU) {
                v0 = fmaxf(v0, 0.f); v1 = fmaxf(v1, 0.f);
                v2 = fmaxf(v2, 0.f); v3 = fmaxf(v3, 0.f);
            }
            size_t oa = (size_t)rowa * N + col;
            size_t ob = (size_t)(rowa + 8) * N + col;
            if (WF32) {
                *(float2*)(oF + oa) = make_float2(v0, v1);
                *(float2*)(oF + ob) = make_float2(v2, v3);
            }
            if (WSPL) {
                bf16 h0, h1, h2, h3, l0, l1, l2, l3;
                split2(v0, h0, l0); split2(v1, h1, l1);
                split2(v2, h2, l2); split2(v3, h3, l3);
                __nv_bfloat162 ha; ha.x = h0; ha.y = h1;
                __nv_bfloat162 hb; hb.x = h2; hb.y = h3;
                __nv_bfloat162 la; la.x = l0; la.y = l1;
                __nv_bfloat162 lb; lb.x = l2; lb.y = l3;
                *(__nv_bfloat162*)(oH + oa) = ha;
                *(__nv_bfloat162*)(oH + ob) = hb;
                *(__nv_bfloat162*)(oL + oa) = la;
                *(__nv_bfloat162*)(oL + ob) = lb;
            }
        }
    }
}

// ============================================================
// fp32 -> (bf16 hi, bf16 lo) split, float4-vectorized
// ============================================================
__global__ __launch_bounds__(256)
void split_kernel(const float4* __restrict__ in, bf16* __restrict__ hi,
                  bf16* __restrict__ lo, int n4)
{
    int i = blockIdx.x * 256 + threadIdx.x;
    if (i >= n4) return;
    float4 v = in[i];
    bf16 h0, h1, h2, h3, l0, l1, l2, l3;
    split2(v.x, h0, l0); split2(v.y, h1, l1);
    split2(v.z, h2, l2); split2(v.w, h3, l3);
    __nv_bfloat162 hA; hA.x = h0; hA.y = h1;
    __nv_bfloat162 hB; hB.x = h2; hB.y = h3;
    __nv_bfloat162 lA; lA.x = l0; lA.y = l1;
    __nv_bfloat162 lB; lB.x = l2; lB.y = l3;
    *(__nv_bfloat162*)(hi + (size_t)i * 4)     = hA;
    *(__nv_bfloat162*)(hi + (size_t)i * 4 + 2) = hB;
    *(__nv_bfloat162*)(lo + (size_t)i * 4)     = lA;
    *(__nv_bfloat162*)(lo + (size_t)i * 4 + 2) = lB;
}

// ============================================================
// transpose + split: in [R,C] fp32 -> hi/lo [C,R] bf16
// ============================================================
__global__ __launch_bounds__(256)
void tsplit_kernel(const float* __restrict__ in, bf16* __restrict__ hi,
                   bf16* __restrict__ lo, int R, int C)
{
    __shared__ float t[32][33];
    int r0 = blockIdx.x * 32, c0 = blockIdx.y * 32;
    int tx = threadIdx.x, ty = threadIdx.y;   // (32, 8)
    #pragma unroll
    for (int i = 0; i < 32; i += 8)
        t[ty + i][tx] = in[(size_t)(r0 + ty + i) * C + c0 + tx];
    __syncthreads();
    #pragma unroll
    for (int i = 0; i < 32; i += 8) {
        float v = t[tx][ty + i];
        bf16 h, l;
        split2(v, h, l);
        size_t o = (size_t)(c0 + ty + i) * R + r0 + tx;
        hi[o] = h;
        lo[o] = l;
    }
}

// ============================================================
// inverse norms of emb rows
// ============================================================
__global__ __launch_bounds__(256)
void prep_invn_kernel(const float* __restrict__ emb, float* __restrict__ invn)
{
    int c = blockIdx.x, t = threadIdx.x;
    float v = emb[(size_t)c * EMB + t];
    __shared__ float red[256];
    red[t] = v * v;
    __syncthreads();
    #pragma unroll
    for (int off = 128; off > 0; off >>= 1) {
        if (t < off) red[t] += red[t + off];
        __syncthreads();
    }
    if (t == 0) invn[c] = 1.f / (sqrtf(red[0]) + 1e-12f);
}

// ============================================================
// VQ: argmax over sim*invn, one-hot, codebook gather (fp32 + split)
// ============================================================
__global__ __launch_bounds__(256)
void vq_kernel(const float* __restrict__ sim, const float* __restrict__ invn,
               const float* __restrict__ emb,
               const bf16* __restrict__ emb_hi, const bf16* __restrict__ emb_lo,
               float* __restrict__ vq_feat, float* __restrict__ onehot,
               bf16* __restrict__ vq_hi, bf16* __restrict__ vq_lo)
{
    int row = blockIdx.x;
    int t = threadIdx.x;
    const float* s = sim + (size_t)row * KCODE;

    float v0 = s[t] * invn[t];
    float v1 = s[t + 256] * invn[t + 256];
    float bv; int bi;
    if (v0 >= v1) { bv = v0; bi = t; } else { bv = v1; bi = t + 256; }

    __shared__ float sv[256];
    __shared__ int   si[256];
    sv[t] = bv; si[t] = bi;
    __syncthreads();
    #pragma unroll
    for (int off = 128; off > 0; off >>= 1) {
        if (t < off) {
            float ov = sv[t + off]; int oi = si[t + off];
            if (ov > sv[t] || (ov == sv[t] && oi < si[t])) { sv[t] = ov; si[t] = oi; }
        }
        __syncthreads();
    }
    int idx = si[0];

    onehot[(size_t)row * KCODE + t]       = (t == idx)       ? 1.f : 0.f;
    onehot[(size_t)row * KCODE + t + 256] = (t + 256 == idx) ? 1.f : 0.f;
    vq_feat[(size_t)row * EMB + t] = emb[(size_t)idx * EMB + t];
    vq_hi[(size_t)row * EMB + t]   = emb_hi[(size_t)idx * EMB + t];
    vq_lo[(size_t)row * EMB + t]   = emb_lo[(size_t)idx * EMB + t];
}

// ============================================================
// launcher
// ============================================================
extern "C" void kernel_launch(void* const* d_in, const int* in_sizes, int n_in,
                              void* d_out, int out_size)
{
    const float* x      = (const float*)d_in[0];
    const float* enc_w1 = (const float*)d_in[1];
    const float* enc_b1 = (const float*)d_in[2];
    const float* enc_w2 = (const float*)d_in[3];
    const float* enc_b2 = (const float*)d_in[4];
    const float* emb    = (const float*)d_in[5];
    const float* dec_w1 = (const float*)d_in[6];
    const float* dec_b1 = (const float*)d_in[7];
    const float* dec_w2 = (const float*)d_in[8];
    const float* dec_b2 = (const float*)d_in[9];

    float* out = (float*)d_out;
    float* o_encoded = out;
    float* o_vqfeat  = o_encoded + (size_t)NB * EMB;
    float* o_onehot  = o_vqfeat  + (size_t)NB * EMB;
    float* o_decoded = o_onehot  + (size_t)NB * KCODE;
    float* o_emb     = o_decoded + (size_t)NB * FEAT;

    bf16 *x_hi, *x_lo, *w1t_hi, *w1t_lo, *w2t_hi, *w2t_lo, *d1t_hi, *d1t_lo,
         *d2t_hi, *d2t_lo, *emb_hi, *emb_lo, *h_hi, *h_lo, *e_hi, *e_lo,
         *v_hi, *v_lo, *dd_hi, *dd_lo;
    float *sim, *invn;
    cudaGetSymbolAddress((void**)&x_hi, g_x_hi);     cudaGetSymbolAddress((void**)&x_lo, g_x_lo);
    cudaGetSymbolAddress((void**)&w1t_hi, g_w1t_hi); cudaGetSymbolAddress((void**)&w1t_lo, g_w1t_lo);
    cudaGetSymbolAddress((void**)&w2t_hi, g_w2t_hi); cudaGetSymbolAddress((void**)&w2t_lo, g_w2t_lo);
    cudaGetSymbolAddress((void**)&d1t_hi, g_d1t_hi); cudaGetSymbolAddress((void**)&d1t_lo, g_d1t_lo);
    cudaGetSymbolAddress((void**)&d2t_hi, g_d2t_hi); cudaGetSymbolAddress((void**)&d2t_lo, g_d2t_lo);
    cudaGetSymbolAddress((void**)&emb_hi, g_emb_hi); cudaGetSymbolAddress((void**)&emb_lo, g_emb_lo);
    cudaGetSymbolAddress((void**)&h_hi, g_h_hi);     cudaGetSymbolAddress((void**)&h_lo, g_h_lo);
    cudaGetSymbolAddress((void**)&e_hi, g_e_hi);     cudaGetSymbolAddress((void**)&e_lo, g_e_lo);
    cudaGetSymbolAddress((void**)&v_hi, g_v_hi);     cudaGetSymbolAddress((void**)&v_lo, g_v_lo);
    cudaGetSymbolAddress((void**)&dd_hi, g_dd_hi);   cudaGetSymbolAddress((void**)&dd_lo, g_dd_lo);
    cudaGetSymbolAddress((void**)&sim, g_sim);       cudaGetSymbolAddress((void**)&invn, g_invn);

    cudaFuncSetAttribute(tgemm<true,  true,  false, true >, cudaFuncAttributeMaxDynamicSharedMemorySize, SMEM_SZ);
    cudaFuncSetAttribute(tgemm<false, true,  true,  true >, cudaFuncAttributeMaxDynamicSharedMemorySize, SMEM_SZ);
    cudaFuncSetAttribute(tgemm<false, false, true,  false>, cudaFuncAttributeMaxDynamicSharedMemorySize, SMEM_SZ);
    cudaFuncSetAttribute(tgemm<true,  true,  true,  false>, cudaFuncAttributeMaxDynamicSharedMemorySize, SMEM_SZ);

    // ---- input conversions ----
    split_kernel<<<(NB * FEAT / 4) / 256, 256>>>((const float4*)x, x_hi, x_lo, NB * FEAT / 4);
    split_kernel<<<(KCODE * EMB / 4) / 256, 256>>>((const float4*)emb, emb_hi, emb_lo, KCODE * EMB / 4);
    tsplit_kernel<<<dim3(FEAT / 32, MID / 32),  dim3(32, 8)>>>(enc_w1, w1t_hi, w1t_lo, FEAT, MID);
    tsplit_kernel<<<dim3(MID / 32,  EMB / 32),  dim3(32, 8)>>>(enc_w2, w2t_hi, w2t_lo, MID,  EMB);
    tsplit_kernel<<<dim3(EMB / 32,  MID / 32),  dim3(32, 8)>>>(dec_w1, d1t_hi, d1t_lo, EMB,  MID);
    tsplit_kernel<<<dim3(MID / 32,  FEAT / 32), dim3(32, 8)>>>(dec_w2, d2t_hi, d2t_lo, MID,  FEAT);
    prep_invn_kernel<<<KCODE, 256>>>(emb, invn);

    // ---- GEMM chain (HMMA mma.sync, split-bf16) ----
    // h = relu(x @ enc_w1 + b1) -> split
    tgemm<true, true, false, true><<<dim3(MID / BN, NB / BM), 256, SMEM_SZ>>>(
        x_hi, x_lo, w1t_hi, w1t_lo, enc_b1, nullptr, h_hi, h_lo, NB, MID, FEAT);
    // encoded = h @ enc_w2 + b2 -> fp32 out + split
    tgemm<false, true, true, true><<<dim3(EMB / BN, NB / BM), 256, SMEM_SZ>>>(
        h_hi, h_lo, w2t_hi, w2t_lo, enc_b2, o_encoded, e_hi, e_lo, NB, EMB, MID);
    // sim = encoded @ emb^T
    tgemm<false, false, true, false><<<dim3(KCODE / BN, NB / BM), 256, SMEM_SZ>>>(
        e_hi, e_lo, emb_hi, emb_lo, nullptr, sim, nullptr, nullptr, NB, KCODE, EMB);
    // VQ
    vq_kernel<<<NB, 256>>>(sim, invn, emb, emb_hi, emb_lo, o_vqfeat, o_onehot, v_hi, v_lo);
    // d = relu(vq @ dec_w1 + b1) -> split
    tgemm<true, true, false, true><<<dim3(MID / BN, NB / BM), 256, SMEM_SZ>>>(
        v_hi, v_lo, d1t_hi, d1t_lo, dec_b1, nullptr, dd_hi, dd_lo, NB, MID, EMB);
    // decoded = relu(d @ dec_w2 + b2) -> fp32 out
    tgemm<true, true, true, false><<<dim3(FEAT / BN, NB / BM), 256, SMEM_SZ>>>(
        dd_hi, dd_lo, d2t_hi, d2t_lo, dec_b2, o_decoded, nullptr, nullptr, NB, FEAT, MID);

    cudaMemcpyAsync(o_emb, emb, (size_t)KCODE * EMB * sizeof(float),
                    cudaMemcpyDeviceToDevice, 0);
}

// round 5
// speedup vs baseline: 3.1946x; 1.1407x over previous
#include <cuda_runtime.h>
#include <cuda_bf16.h>
#include <cuda_fp16.h>
#include <math.h>
#include <stdint.h>

#define NB    8192
#define FEAT  4096
#define MID   512
#define EMB   256
#define KCODE 512

typedef __nv_bfloat16 bf16;
typedef __half fp16;

// ------------- scratch (__device__ globals; no allocs allowed) -------------
__device__ bf16 g_x_hi[NB*FEAT],  g_x_lo[NB*FEAT];
__device__ bf16 g_w1t_hi[MID*FEAT], g_w1t_lo[MID*FEAT];   // enc_w1^T [512,4096]
__device__ bf16 g_w2t_hi[EMB*MID],  g_w2t_lo[EMB*MID];    // enc_w2^T [256,512]
__device__ fp16 g_d1t_hi[MID*EMB],  g_d1t_lo[MID*EMB];    // dec_w1^T [512,256] fp16
__device__ fp16 g_d2t_hi[FEAT*MID], g_d2t_lo[FEAT*MID];   // dec_w2^T [4096,512] fp16
__device__ bf16 g_emb_hi[KCODE*EMB], g_emb_lo[KCODE*EMB];
__device__ bf16 g_h_hi[NB*MID],  g_h_lo[NB*MID];
__device__ bf16 g_e_hi[NB*EMB],  g_e_lo[NB*EMB];
__device__ fp16 g_v_hi[NB*EMB],  g_v_lo[NB*EMB];          // vq split fp16
__device__ fp16 g_dd_hi[NB*MID], g_dd_lo[NB*MID];         // dec hidden split fp16
__device__ float g_sim[NB*KCODE];
__device__ float g_invn[KCODE];

// ------------- helpers -------------
__device__ __forceinline__ uint32_t smem_u32(const void* p) {
    uint32_t a;
    asm("{ .reg .u64 t; cvta.to.shared.u64 t, %1; cvt.u32.u64 %0, t; }" : "=r"(a) : "l"(p));
    return a;
}
#define SWZ(o) ((o) ^ (((o) >> 3) & 0x70))
#define CP16(dst, src) asm volatile("cp.async.cg.shared.global [%0], [%1], 16;" :: "r"(dst), "l"(src))

__device__ __forceinline__ void ldsm4(uint32_t* r, uint32_t addr) {
    asm volatile("ldmatrix.sync.aligned.m8n8.x4.shared.b16 {%0,%1,%2,%3}, [%4];"
        : "=r"(r[0]), "=r"(r[1]), "=r"(r[2]), "=r"(r[3]) : "r"(addr));
}
template<typename T>
__device__ __forceinline__ void mma16816(float* c, const uint32_t* a, const uint32_t* b);
template<>
__device__ __forceinline__ void mma16816<bf16>(float* c, const uint32_t* a, const uint32_t* b) {
    asm volatile("mma.sync.aligned.m16n8k16.row.col.f32.bf16.bf16.f32 "
        "{%0,%1,%2,%3}, {%4,%5,%6,%7}, {%8,%9}, {%0,%1,%2,%3};"
        : "+f"(c[0]), "+f"(c[1]), "+f"(c[2]), "+f"(c[3])
        : "r"(a[0]), "r"(a[1]), "r"(a[2]), "r"(a[3]), "r"(b[0]), "r"(b[1]));
}
template<>
__device__ __forceinline__ void mma16816<fp16>(float* c, const uint32_t* a, const uint32_t* b) {
    asm volatile("mma.sync.aligned.m16n8k16.row.col.f32.f16.f16.f32 "
        "{%0,%1,%2,%3}, {%4,%5,%6,%7}, {%8,%9}, {%0,%1,%2,%3};"
        : "+f"(c[0]), "+f"(c[1]), "+f"(c[2]), "+f"(c[3])
        : "r"(a[0]), "r"(a[1]), "r"(a[2]), "r"(a[3]), "r"(b[0]), "r"(b[1]));
}

template<typename T> __device__ __forceinline__ void split2(float v, T& h, T& l);
template<> __device__ __forceinline__ void split2<bf16>(float v, bf16& h, bf16& l) {
    h = __float2bfloat16(v);
    l = __float2bfloat16(v - __bfloat162float(h));
}
template<> __device__ __forceinline__ void split2<fp16>(float v, fp16& h, fp16& l) {
    h = __float2half(v);
    l = __float2half(v - __half2float(h));
}
template<typename T>
__device__ __forceinline__ uint32_t pk2(T a, T b) {
    uint32_t u;
    uint16_t* p = (uint16_t*)&u;
    p[0] = *(uint16_t*)&a; p[1] = *(uint16_t*)&b;
    return u;
}

// ============================================================
// split GEMM on HMMA:  C[M,N] = act(A @ W + bias)
// A = (Ah,Al) [M,K] row-major T ; B = (Bh,Bl) [N,K] row-major T (W^T).
// PASSES==3: C = Ah*Bh + Al*Bh + Ah*Bl ; PASSES==2: C = Ah*Bh + Al*Bh.
// Tile BM=128 x BN=256, BK=64, 256 threads (warps 2x4, warp tile 64x64).
// ============================================================
#define BM 128
#define BN 256
#define BK 64
#define OFF_AH 0
#define OFF_AL 16384
#define OFF_BH 32768
#define OFF_BL 65536

template<typename T, int PASSES>
__device__ __forceinline__ void load_chunk(
    uint32_t st, const T* __restrict__ Ah, const T* __restrict__ Al,
    const T* __restrict__ Bh, const T* __restrict__ Bl,
    int m0, int n0, int k0, int K, int tid)
{
    const T* pAh = Ah + (size_t)m0 * K + k0;
    const T* pAl = Al + (size_t)m0 * K + k0;
    #pragma unroll
    for (int i = 0; i < 4; i++) {             // A: 128 rows x 8 x 16B
        int u = i * 256 + tid;
        int r = u >> 3, c = u & 7;
        uint32_t so = SWZ((uint32_t)(r * 128 + c * 16));
        size_t go = (size_t)r * K + c * 8;
        CP16(st + OFF_AH + so, pAh + go);
        CP16(st + OFF_AL + so, pAl + go);
    }
    const T* pBh = Bh + (size_t)n0 * K + k0;
    #pragma unroll
    for (int i = 0; i < 8; i++) {             // B: 256 rows x 8 x 16B
        int u = i * 256 + tid;
        int r = u >> 3, c = u & 7;
        uint32_t so = SWZ((uint32_t)(r * 128 + c * 16));
        size_t go = (size_t)r * K + c * 8;
        CP16(st + OFF_BH + so, pBh + go);
        if (PASSES == 3) {
            const T* pBl = Bl + (size_t)n0 * K + k0;
            CP16(st + OFF_BL + so, pBl + go);
        }
    }
}

template<bool RELU, bool HASBIAS, bool WF32, bool WSPL, typename T, int PASSES>
__global__ __launch_bounds__(256, 1)
void tgemm(const T* __restrict__ Ah, const T* __restrict__ Al,
           const T* __restrict__ Bh, const T* __restrict__ Bl,
           const float* __restrict__ bias,
           float* __restrict__ oF, T* __restrict__ oH, T* __restrict__ oL,
           int M, int N, int K)
{
    constexpr int STAGE = (PASSES == 3) ? 98304 : 65536;
    extern __shared__ char smem[];
    const uint32_t sb = smem_u32(smem);
    const int tid  = threadIdx.x;
    const int wid  = tid >> 5;
    const int lane = tid & 31;
    const int wm   = wid >> 2;     // 0..1
    const int wn   = wid & 3;      // 0..3
    const int m0   = blockIdx.y * BM;
    const int n0   = blockIdx.x * BN;
    const int NC   = K / BK;

    float acc[4][8][4];
    #pragma unroll
    for (int i = 0; i < 4; i++)
        #pragma unroll
        for (int j = 0; j < 8; j++)
            #pragma unroll
            for (int k = 0; k < 4; k++) acc[i][j][k] = 0.f;

    load_chunk<T, PASSES>(sb, Ah, Al, Bh, Bl, m0, n0, 0, K, tid);
    asm volatile("cp.async.commit_group;" ::: "memory");

    const int g  = lane >> 3;
    const int lr = lane & 7;

    for (int c = 0; c < NC; c++) {
        if (c + 1 < NC) {
            load_chunk<T, PASSES>(sb + ((c + 1) & 1) * STAGE, Ah, Al, Bh, Bl,
                                  m0, n0, (c + 1) * BK, K, tid);
            asm volatile("cp.async.commit_group;" ::: "memory");
            asm volatile("cp.async.wait_group 1;" ::: "memory");
        } else {
            asm volatile("cp.async.wait_group 0;" ::: "memory");
        }
        __syncthreads();

        const uint32_t st = sb + (c & 1) * STAGE;
        #pragma unroll
        for (int ks = 0; ks < 4; ks++) {
            uint32_t afh[16], afl[16], bfr[16];
            #pragma unroll
            for (int mt = 0; mt < 4; mt++) {
                int row = wm * 64 + mt * 16 + (g & 1) * 8 + lr;
                int k   = ks * 16 + (g >> 1) * 8;
                uint32_t off = SWZ((uint32_t)(row * 128 + k * 2));
                ldsm4(&afh[mt * 4], st + OFF_AH + off);
                ldsm4(&afl[mt * 4], st + OFF_AL + off);
            }
            #pragma unroll
            for (int p = 0; p < 4; p++) {
                int row = wn * 64 + (p * 2 + (g >> 1)) * 8 + lr;
                int k   = ks * 16 + (g & 1) * 8;
                uint32_t off = SWZ((uint32_t)(row * 128 + k * 2));
                ldsm4(&bfr[p * 4], st + OFF_BH + off);
            }
            #pragma unroll
            for (int mt = 0; mt < 4; mt++)
                #pragma unroll
                for (int nt = 0; nt < 8; nt++)
                    mma16816<T>(acc[mt][nt], &afh[mt * 4], &bfr[(nt >> 1) * 4 + (nt & 1) * 2]);
            #pragma unroll
            for (int mt = 0; mt < 4; mt++)
                #pragma unroll
                for (int nt = 0; nt < 8; nt++)
                    mma16816<T>(acc[mt][nt], &afl[mt * 4], &bfr[(nt >> 1) * 4 + (nt & 1) * 2]);
            if (PASSES == 3) {
                #pragma unroll
                for (int p = 0; p < 4; p++) {
                    int row = wn * 64 + (p * 2 + (g >> 1)) * 8 + lr;
                    int k   = ks * 16 + (g & 1) * 8;
                    uint32_t off = SWZ((uint32_t)(row * 128 + k * 2));
                    ldsm4(&bfr[p * 4], st + OFF_BL + off);
                }
                #pragma unroll
                for (int mt = 0; mt < 4; mt++)
                    #pragma unroll
                    for (int nt = 0; nt < 8; nt++)
                        mma16816<T>(acc[mt][nt], &afh[mt * 4], &bfr[(nt >> 1) * 4 + (nt & 1) * 2]);
            }
        }
        __syncthreads();
    }

    // ---- epilogue ----
    const int r0 = lane >> 2;
    const int c0 = (lane & 3) * 2;
    #pragma unroll
    for (int nt = 0; nt < 8; nt++) {
        int col = n0 + wn * 64 + nt * 8 + c0;
        float b0 = 0.f, b1 = 0.f;
        if (HASBIAS) { b0 = __ldg(&bias[col]); b1 = __ldg(&bias[col + 1]); }
        #pragma unroll
        for (int mt = 0; mt < 4; mt++) {
            int rowa = m0 + wm * 64 + mt * 16 + r0;
            float v0 = acc[mt][nt][0] + b0;
            float v1 = acc[mt][nt][1] + b1;
            float v2 = acc[mt][nt][2] + b0;
            float v3 = acc[mt][nt][3] + b1;
            if (RELU) {
                v0 = fmaxf(v0, 0.f); v1 = fmaxf(v1, 0.f);
                v2 = fmaxf(v2, 0.f); v3 = fmaxf(v3, 0.f);
            }
            size_t oa = (size_t)rowa * N + col;
            size_t ob = (size_t)(rowa + 8) * N + col;
            if (WF32) {
                *(float2*)(oF + oa) = make_float2(v0, v1);
                *(float2*)(oF + ob) = make_float2(v2, v3);
            }
            if (WSPL) {
                T h0, h1, h2, h3, l0, l1, l2, l3;
                split2<T>(v0, h0, l0); split2<T>(v1, h1, l1);
                split2<T>(v2, h2, l2); split2<T>(v3, h3, l3);
                *(uint32_t*)(oH + oa) = pk2(h0, h1);
                *(uint32_t*)(oH + ob) = pk2(h2, h3);
                *(uint32_t*)(oL + oa) = pk2(l0, l1);
                *(uint32_t*)(oL + ob) = pk2(l2, l3);
            }
        }
    }
}

// ============================================================
// fp32 -> (hi, lo) split, float4-vectorized
// ============================================================
__global__ __launch_bounds__(256)
void split_kernel(const float4* __restrict__ in, bf16* __restrict__ hi,
                  bf16* __restrict__ lo, int n4)
{
    int i = blockIdx.x * 256 + threadIdx.x;
    if (i >= n4) return;
    float4 v = in[i];
    bf16 h0, h1, h2, h3, l0, l1, l2, l3;
    split2<bf16>(v.x, h0, l0); split2<bf16>(v.y, h1, l1);
    split2<bf16>(v.z, h2, l2); split2<bf16>(v.w, h3, l3);
    *(uint32_t*)(hi + (size_t)i * 4)     = pk2(h0, h1);
    *(uint32_t*)(hi + (size_t)i * 4 + 2) = pk2(h2, h3);
    *(uint32_t*)(lo + (size_t)i * 4)     = pk2(l0, l1);
    *(uint32_t*)(lo + (size_t)i * 4 + 2) = pk2(l2, l3);
}

// ============================================================
// transpose + split: in [R,C] fp32 -> hi/lo [C,R] T
// ============================================================
template<typename T>
__global__ __launch_bounds__(256)
void tsplit_kernel(const float* __restrict__ in, T* __restrict__ hi,
                   T* __restrict__ lo, int R, int C)
{
    __shared__ float t[32][33];
    int r0 = blockIdx.x * 32, c0 = blockIdx.y * 32;
    int tx = threadIdx.x, ty = threadIdx.y;
    #pragma unroll
    for (int i = 0; i < 32; i += 8)
        t[ty + i][tx] = in[(size_t)(r0 + ty + i) * C + c0 + tx];
    __syncthreads();
    #pragma unroll
    for (int i = 0; i < 32; i += 8) {
        float v = t[tx][ty + i];
        T h, l;
        split2<T>(v, h, l);
        size_t o = (size_t)(c0 + ty + i) * R + r0 + tx;
        hi[o] = h;
        lo[o] = l;
    }
}

// ============================================================
// inverse norms of emb rows
// ============================================================
__global__ __launch_bounds__(256)
void prep_invn_kernel(const float* __restrict__ emb, float* __restrict__ invn)
{
    int c = blockIdx.x, t = threadIdx.x;
    float v = emb[(size_t)c * EMB + t];
    __shared__ float red[256];
    red[t] = v * v;
    __syncthreads();
    #pragma unroll
    for (int off = 128; off > 0; off >>= 1) {
        if (t < off) red[t] += red[t + off];
        __syncthreads();
    }
    if (t == 0) invn[c] = 1.f / (sqrtf(red[0]) + 1e-12f);
}

// ============================================================
// VQ: argmax over sim*invn, one-hot, codebook gather (fp32 + fp16 split)
// ============================================================
__global__ __launch_bounds__(256)
void vq_kernel(const float* __restrict__ sim, const float* __restrict__ invn,
               const float* __restrict__ emb,
               float* __restrict__ vq_feat, float* __restrict__ onehot,
               fp16* __restrict__ vq_hi, fp16* __restrict__ vq_lo)
{
    int row = blockIdx.x;
    int t = threadIdx.x;
    const float* s = sim + (size_t)row * KCODE;

    float v0 = s[t] * invn[t];
    float v1 = s[t + 256] * invn[t + 256];
    float bv; int bi;
    if (v0 >= v1) { bv = v0; bi = t; } else { bv = v1; bi = t + 256; }

    __shared__ float sv[256];
    __shared__ int   si[256];
    sv[t] = bv; si[t] = bi;
    __syncthreads();
    #pragma unroll
    for (int off = 128; off > 0; off >>= 1) {
        if (t < off) {
            float ov = sv[t + off]; int oi = si[t + off];
            if (ov > sv[t] || (ov == sv[t] && oi < si[t])) { sv[t] = ov; si[t] = oi; }
        }
        __syncthreads();
    }
    int idx = si[0];

    onehot[(size_t)row * KCODE + t]       = (t == idx)       ? 1.f : 0.f;
    onehot[(size_t)row * KCODE + t + 256] = (t + 256 == idx) ? 1.f : 0.f;
    float ev = emb[(size_t)idx * EMB + t];
    vq_feat[(size_t)row * EMB + t] = ev;
    fp16 h, l;
    split2<fp16>(ev, h, l);
    vq_hi[(size_t)row * EMB + t] = h;
    vq_lo[(size_t)row * EMB + t] = l;
}

// ============================================================
// launcher
// ============================================================
extern "C" void kernel_launch(void* const* d_in, const int* in_sizes, int n_in,
                              void* d_out, int out_size)
{
    const float* x      = (const float*)d_in[0];
    const float* enc_w1 = (const float*)d_in[1];
    const float* enc_b1 = (const float*)d_in[2];
    const float* enc_w2 = (const float*)d_in[3];
    const float* enc_b2 = (const float*)d_in[4];
    const float* emb    = (const float*)d_in[5];
    const float* dec_w1 = (const float*)d_in[6];
    const float* dec_b1 = (const float*)d_in[7];
    const float* dec_w2 = (const float*)d_in[8];
    const float* dec_b2 = (const float*)d_in[9];

    float* out = (float*)d_out;
    float* o_encoded = out;
    float* o_vqfeat  = o_encoded + (size_t)NB * EMB;
    float* o_onehot  = o_vqfeat  + (size_t)NB * EMB;
    float* o_decoded = o_onehot  + (size_t)NB * KCODE;
    float* o_emb     = o_decoded + (size_t)NB * FEAT;

    bf16 *x_hi, *x_lo, *w1t_hi, *w1t_lo, *w2t_hi, *w2t_lo, *emb_hi, *emb_lo,
         *h_hi, *h_lo, *e_hi, *e_lo;
    fp16 *d1t_hi, *d1t_lo, *d2t_hi, *d2t_lo, *v_hi, *v_lo, *dd_hi, *dd_lo;
    float *sim, *invn;
    cudaGetSymbolAddress((void**)&x_hi, g_x_hi);     cudaGetSymbolAddress((void**)&x_lo, g_x_lo);
    cudaGetSymbolAddress((void**)&w1t_hi, g_w1t_hi); cudaGetSymbolAddress((void**)&w1t_lo, g_w1t_lo);
    cudaGetSymbolAddress((void**)&w2t_hi, g_w2t_hi); cudaGetSymbolAddress((void**)&w2t_lo, g_w2t_lo);
    cudaGetSymbolAddress((void**)&d1t_hi, g_d1t_hi); cudaGetSymbolAddress((void**)&d1t_lo, g_d1t_lo);
    cudaGetSymbolAddress((void**)&d2t_hi, g_d2t_hi); cudaGetSymbolAddress((void**)&d2t_lo, g_d2t_lo);
    cudaGetSymbolAddress((void**)&emb_hi, g_emb_hi); cudaGetSymbolAddress((void**)&emb_lo, g_emb_lo);
    cudaGetSymbolAddress((void**)&h_hi, g_h_hi);     cudaGetSymbolAddress((void**)&h_lo, g_h_lo);
    cudaGetSymbolAddress((void**)&e_hi, g_e_hi);     cudaGetSymbolAddress((void**)&e_lo, g_e_lo);
    cudaGetSymbolAddress((void**)&v_hi, g_v_hi);     cudaGetSymbolAddress((void**)&v_lo, g_v_lo);
    cudaGetSymbolAddress((void**)&dd_hi, g_dd_hi);   cudaGetSymbolAddress((void**)&dd_lo, g_dd_lo);
    cudaGetSymbolAddress((void**)&sim, g_sim);       cudaGetSymbolAddress((void**)&invn, g_invn);

    const int SM3 = 2 * 98304;   // 3-pass stages
    const int SM2 = 2 * 65536;   // 2-pass stages
    cudaFuncSetAttribute(tgemm<true,  true,  false, true,  bf16, 3>, cudaFuncAttributeMaxDynamicSharedMemorySize, SM3);
    cudaFuncSetAttribute(tgemm<false, true,  true,  true,  bf16, 3>, cudaFuncAttributeMaxDynamicSharedMemorySize, SM3);
    cudaFuncSetAttribute(tgemm<false, false, true,  false, bf16, 3>, cudaFuncAttributeMaxDynamicSharedMemorySize, SM3);
    cudaFuncSetAttribute(tgemm<true,  true,  false, true,  fp16, 2>, cudaFuncAttributeMaxDynamicSharedMemorySize, SM2);
    cudaFuncSetAttribute(tgemm<true,  true,  true,  false, fp16, 2>, cudaFuncAttributeMaxDynamicSharedMemorySize, SM2);

    // launches ordered so GEMM1 is the 6th kernel launch (ncu -s 5 -c 1 captures it)
    // 1) x split
    split_kernel<<<(NB * FEAT / 4) / 256, 256>>>((const float4*)x, x_hi, x_lo, NB * FEAT / 4);
    // 2) enc_w1^T split
    tsplit_kernel<bf16><<<dim3(FEAT / 32, MID / 32),  dim3(32, 8)>>>(enc_w1, w1t_hi, w1t_lo, FEAT, MID);
    // 3) emb split (for sim GEMM B operand)
    split_kernel<<<(KCODE * EMB / 4) / 256, 256>>>((const float4*)emb, emb_hi, emb_lo, KCODE * EMB / 4);
    // 4) enc_w2^T split
    tsplit_kernel<bf16><<<dim3(MID / 32,  EMB / 32),  dim3(32, 8)>>>(enc_w2, w2t_hi, w2t_lo, MID,  EMB);
    // 5) inv norms
    prep_invn_kernel<<<KCODE, 256>>>(emb, invn);
    // 6) GEMM1: h = relu(x @ enc_w1 + b1)  [PROFILED]
    tgemm<true, true, false, true, bf16, 3><<<dim3(MID / BN, NB / BM), 256, SM3>>>(
        x_hi, x_lo, w1t_hi, w1t_lo, enc_b1, nullptr, h_hi, h_lo, NB, MID, FEAT);
    // 7) GEMM2: encoded = h @ enc_w2 + b2
    tgemm<false, true, true, true, bf16, 3><<<dim3(EMB / BN, NB / BM), 256, SM3>>>(
        h_hi, h_lo, w2t_hi, w2t_lo, enc_b2, o_encoded, e_hi, e_lo, NB, EMB, MID);
    // 8) sim = encoded @ emb^T
    tgemm<false, false, true, false, bf16, 3><<<dim3(KCODE / BN, NB / BM), 256, SM3>>>(
        e_hi, e_lo, emb_hi, emb_lo, nullptr, sim, nullptr, nullptr, NB, KCODE, EMB);
    // 9) VQ
    vq_kernel<<<NB, 256>>>(sim, invn, emb, o_vqfeat, o_onehot, v_hi, v_lo);
    // 10) dec_w1^T split (fp16)
    tsplit_kernel<fp16><<<dim3(EMB / 32,  MID / 32),  dim3(32, 8)>>>(dec_w1, d1t_hi, d1t_lo, EMB,  MID);
    // 11) GEMM4: d = relu(vq @ dec_w1 + b1)  (2-pass fp16)
    tgemm<true, true, false, true, fp16, 2><<<dim3(MID / BN, NB / BM), 256, SM2>>>(
        v_hi, v_lo, d1t_hi, d1t_lo, dec_b1, nullptr, dd_hi, dd_lo, NB, MID, EMB);
    // 12) dec_w2^T split (fp16)
    tsplit_kernel<fp16><<<dim3(MID / 32,  FEAT / 32), dim3(32, 8)>>>(dec_w2, d2t_hi, d2t_lo, MID,  FEAT);
    // 13) GEMM5: decoded = relu(d @ dec_w2 + b2)  (2-pass fp16)
    tgemm<true, true, true, false, fp16, 2><<<dim3(FEAT / BN, NB / BM), 256, SM2>>>(
        dd_hi, dd_lo, d2t_hi, d2t_lo, dec_b2, o_decoded, nullptr, nullptr, NB, FEAT, MID);
    // 14) emb passthrough
    cudaMemcpyAsync(o_emb, emb, (size_t)KCODE * EMB * sizeof(float),
                    cudaMemcpyDeviceToDevice, 0);
}